// round 4
// baseline (speedup 1.0000x reference)
#include <cuda_runtime.h>

#define M_MOL 64
#define NA    24
#define P     276
#define T_ROWS 6000
#define TT    48
#define NBLK  125
#define NTHR  384
#define QC    0.22360679774997896f   // sqrt(5)/sig, sig=10
#define C0    0.0166666666666667f    // 5/(3*sig^2)
#define PPAD  288

// ---------------- global scratch ----------------
__device__ float g_Apart [NBLK * M_MOL * P];
__device__ float g_S1part[NBLK * M_MOL];
__device__ float g_Espart[NBLK * M_MOL];
__device__ unsigned g_phase;   // zero-init, monotonic across replays
__device__ int      g_cnt;     // returns to 0 each call

// ---------------- f32x2 helpers ----------------
typedef unsigned long long u64;
__device__ __forceinline__ u64 pk2(float lo, float hi) {
    u64 r; asm("mov.b64 %0, {%1,%2};" : "=l"(r) : "f"(lo), "f"(hi)); return r;
}
__device__ __forceinline__ u64 fma2(u64 a, u64 b, u64 c) {
    u64 d; asm("fma.rn.f32x2 %0, %1, %2, %3;" : "=l"(d) : "l"(a), "l"(b), "l"(c)); return d;
}
__device__ __forceinline__ void upk2(u64 v, float& lo, float& hi) {
    asm("mov.b64 {%0,%1}, %2;" : "=f"(lo), "=f"(hi) : "l"(v));
}

// smem layout (floats):
//  sX   @0      [48][288]  13824
//  sJ   @13824  [48][288]  13824
//  sQx  @27648  [276][64]  17664
//  sW1d @45312  [48][128]   6144   (w1 duplicated pairs; temp Rs before phase A)
//  sW2  @51456  [48][64]    3072
//  sDot @54528  [48][64]    3072
//  sTn  @57600  [48]
//  sTc  @57648  [48]
//  sNrm @57696  [64]        -> 57760 floats = 231040 B
#define SMEM_FLOATS 57760
#define SMEM_BYTES  (SMEM_FLOATS * 4)

__global__ __launch_bounds__(NTHR, 1)
void k_all(const float* __restrict__ Rs, const float* __restrict__ xst,
           const float* __restrict__ Jx, float* __restrict__ out) {
    extern __shared__ float sm[];
    float* sX   = sm;
    float* sJ   = sm + 13824;
    float* sQx  = sm + 27648;
    float* sW1d = sm + 45312;
    float* sW2  = sm + 51456;
    float* sDot = sm + 54528;
    float* sTn  = sm + 57600;
    float* sTc  = sm + 57648;
    float* sNrm = sm + 57696;
    float* sRs  = sW1d;          // Rs staged here until phase A overwrites

    const int tid  = threadIdx.x;
    const int wid  = tid >> 5;
    const int lane = tid & 31;
    const int blk  = blockIdx.x;
    const int t0   = blk * TT;

    // ---- phase 0: stage Rs + train tiles ----
    for (int i = tid; i < M_MOL * NA * 3; i += NTHR) sRs[i] = Rs[i];
    for (int t = wid; t < TT; t += 12) {
        const float4* src = (const float4*)(xst + (size_t)(t0 + t) * P);
        const float4* srj = (const float4*)(Jx  + (size_t)(t0 + t) * P);
        float4* dx = (float4*)(sX + t * PPAD);
        float4* dj = (float4*)(sJ + t * PPAD);
        for (int c = lane; c < 72; c += 32) {
            float4 v, w;
            if (c < 69) { v = src[c]; w = srj[c]; }
            else        { v = make_float4(0.f,0.f,0.f,0.f); w = v; }
            v.x *= QC; v.y *= QC; v.z *= QC; v.w *= QC;
            dx[c] = v; dj[c] = w;
        }
    }
    __syncthreads();

    // ---- phase 1: qxs descriptors + per-t stats ----
    for (int idx = tid; idx < P * M_MOL; idx += NTHR) {
        int p = idx >> 6;
        int m = idx & 63;
        int i = (int)(0.5f * (1.0f + sqrtf(8.0f * (float)p + 1.0f)));
        while (i * (i - 1) / 2 > p) i--;
        while ((i + 1) * i / 2 <= p) i++;
        int j = p - i * (i - 1) / 2;
        const float* a = sRs + (m * NA + i) * 3;
        const float* b = sRs + (m * NA + j) * 3;
        float dx = a[0] - b[0], dy = a[1] - b[1], dz = a[2] - b[2];
        float r2 = dx * dx + dy * dy + dz * dz;
        sQx[p * M_MOL + m] = QC * rsqrtf(r2);
    }
    {
        #pragma unroll
        for (int k = 0; k < 4; k++) {
            int t = wid * 4 + k;
            const float* xr = sX + t * PPAD;
            const float* jr = sJ + t * PPAD;
            float tn = 0.0f, tc = 0.0f;
            for (int c = lane; c < PPAD; c += 32) {
                float x = xr[c];
                tn = fmaf(x, x, tn);
                tc = fmaf(x, jr[c], tc);
            }
            #pragma unroll
            for (int o = 16; o; o >>= 1) {
                tn += __shfl_down_sync(0xffffffffu, tn, o);
                tc += __shfl_down_sync(0xffffffffu, tc, o);
            }
            if (lane == 0) { sTn[t] = tn; sTc[t] = tc; }
        }
    }
    __syncthreads();

    // ---- phase 2: |qxs_m|^2 (conflict-free column sums) ----
    if (tid < M_MOL) {
        float s = 0.0f;
        #pragma unroll 4
        for (int p = 0; p < P; p++) {
            float v = sQx[p * M_MOL + tid];
            s = fmaf(v, v, s);
        }
        sNrm[tid] = s;
    }
    __syncthreads();

    // ---- phase 3: dual GEMM A: G1 = qxs.qxst^T, G2 = qxs.Jx^T (f32x2, m-pairs) ----
    const int ty = tid & 15;
    const int tx = tid >> 4;       // 0..23
    const int m4 = ty * 4;
    const int t2 = tx * 2;

    u64 g1[2][2] = {{0ull,0ull},{0ull,0ull}};
    u64 g2[2][2] = {{0ull,0ull},{0ull,0ull}};
    {
        const float* xr0 = sX + t2 * PPAD;
        const float* xr1 = xr0 + PPAD;
        const float* jr0 = sJ + t2 * PPAD;
        const float* jr1 = jr0 + PPAD;
        #pragma unroll 2
        for (int p = 0; p < P; p += 2) {
            ulonglong2 a0 = *(const ulonglong2*)(sQx + p * M_MOL + m4);
            ulonglong2 a1 = *(const ulonglong2*)(sQx + (p + 1) * M_MOL + m4);
            float2 x0 = *(const float2*)(xr0 + p);
            float2 x1 = *(const float2*)(xr1 + p);
            float2 j0 = *(const float2*)(jr0 + p);
            float2 j1 = *(const float2*)(jr1 + p);
            u64 X0 = pk2(x0.x, x0.x), X1 = pk2(x1.x, x1.x);
            u64 J0 = pk2(j0.x, j0.x), J1 = pk2(j1.x, j1.x);
            g1[0][0] = fma2(a0.x, X0, g1[0][0]);
            g1[1][0] = fma2(a0.y, X0, g1[1][0]);
            g1[0][1] = fma2(a0.x, X1, g1[0][1]);
            g1[1][1] = fma2(a0.y, X1, g1[1][1]);
            g2[0][0] = fma2(a0.x, J0, g2[0][0]);
            g2[1][0] = fma2(a0.y, J0, g2[1][0]);
            g2[0][1] = fma2(a0.x, J1, g2[0][1]);
            g2[1][1] = fma2(a0.y, J1, g2[1][1]);
            u64 X0b = pk2(x0.y, x0.y), X1b = pk2(x1.y, x1.y);
            u64 J0b = pk2(j0.y, j0.y), J1b = pk2(j1.y, j1.y);
            g1[0][0] = fma2(a1.x, X0b, g1[0][0]);
            g1[1][0] = fma2(a1.y, X0b, g1[1][0]);
            g1[0][1] = fma2(a1.x, X1b, g1[0][1]);
            g1[1][1] = fma2(a1.y, X1b, g1[1][1]);
            g2[0][0] = fma2(a1.x, J0b, g2[0][0]);
            g2[1][0] = fma2(a1.y, J0b, g2[1][0]);
            g2[0][1] = fma2(a1.x, J1b, g2[0][1]);
            g2[1][1] = fma2(a1.y, J1b, g2[1][1]);
        }
    }

    // ---- phase 4: weights (overwrites sRs region via sW1d) ----
    #pragma unroll
    for (int mp = 0; mp < 2; mp++) {
        #pragma unroll
        for (int j = 0; j < 2; j++) {
            int t = t2 + j;
            float tn = sTn[t], tc = sTc[t];
            float G1lo, G1hi, G2lo, G2hi;
            upk2(g1[mp][j], G1lo, G1hi);
            upk2(g2[mp][j], G2lo, G2hi);
            #pragma unroll
            for (int h = 0; h < 2; h++) {
                int m = m4 + 2 * mp + h;
                float G1 = h ? G1hi : G1lo;
                float G2 = h ? G2hi : G2lo;
                float d2   = fmaf(-2.0f, G1, sNrm[m] + tn);
                float dist = sqrtf(fmaxf(d2, 0.0f));
                float e    = C0 * __expf(-dist);
                float dot  = G2 - tc;
                float w1   = e * dot;
                float w2   = fmaf(e, dist, e);
                *(u64*)&sW1d[t * 128 + 2 * m] = pk2(w1, w1);
                sW2 [t * M_MOL + m] = w2;
                sDot[t * M_MOL + m] = dot;
            }
        }
    }
    __syncthreads();

    // ---- phase 5a: deterministic per-block S1/Es partials ----
    if (tid < M_MOL) {
        float s1 = 0.0f, es = 0.0f;
        #pragma unroll 8
        for (int t = 0; t < TT; t++) {
            s1 += sW1d[t * 128 + 2 * tid];
            es  = fmaf(sW2[t * M_MOL + tid], sDot[t * M_MOL + tid], es);
        }
        g_S1part[blk * M_MOL + tid] = s1;
        g_Espart[blk * M_MOL + tid] = es;
    }

    // ---- phase 5b: GEMM B: A[m,p] = sum_t (w1*qxst + w2*Jx) (f32x2, p-pairs) ----
    const int pg = tid >> 4;        // 0..23 (pg 23 = padding)
    const int p0 = pg * 12;
    u64 acc[4][6];
    #pragma unroll
    for (int mi = 0; mi < 4; mi++)
        #pragma unroll
        for (int pp = 0; pp < 6; pp++) acc[mi][pp] = 0ull;

    #pragma unroll 2
    for (int t = 0; t < TT; t++) {
        const float* xb = sX + t * PPAD + p0;
        const float* jb = sJ + t * PPAD + p0;
        ulonglong2 xA = *(const ulonglong2*)(xb);
        ulonglong2 xB = *(const ulonglong2*)(xb + 4);
        ulonglong2 xC = *(const ulonglong2*)(xb + 8);
        ulonglong2 jA = *(const ulonglong2*)(jb);
        ulonglong2 jB = *(const ulonglong2*)(jb + 4);
        ulonglong2 jC = *(const ulonglong2*)(jb + 8);
        u64 xp[6] = {xA.x, xA.y, xB.x, xB.y, xC.x, xC.y};
        u64 jp[6] = {jA.x, jA.y, jB.x, jB.y, jC.x, jC.y};
        u64 w1d[4], w2d[4];
        float4 w2q = *(const float4*)&sW2[t * M_MOL + m4];
        w2d[0] = pk2(w2q.x, w2q.x); w2d[1] = pk2(w2q.y, w2q.y);
        w2d[2] = pk2(w2q.z, w2q.z); w2d[3] = pk2(w2q.w, w2q.w);
        #pragma unroll
        for (int mi = 0; mi < 4; mi++)
            w1d[mi] = *(const u64*)&sW1d[t * 128 + 2 * (m4 + mi)];
        #pragma unroll
        for (int mi = 0; mi < 4; mi++)
            #pragma unroll
            for (int pp = 0; pp < 6; pp++)
                acc[mi][pp] = fma2(w1d[mi], xp[pp], fma2(w2d[mi], jp[pp], acc[mi][pp]));
    }
    __syncthreads();

    // ---- phase 6: stage acc -> smem -> coalesced global write ----
    float* sAcc = sm;   // sX+sJ region now dead (17664 < 27648)
    if (pg < 23) {
        #pragma unroll
        for (int mi = 0; mi < 4; mi++) {
            #pragma unroll
            for (int pp = 0; pp < 6; pp++) {
                float lo, hi;
                upk2(acc[mi][pp], lo, hi);
                sAcc[(m4 + mi) * P + p0 + 2 * pp]     = lo;
                sAcc[(m4 + mi) * P + p0 + 2 * pp + 1] = hi;
            }
        }
    }
    __syncthreads();
    {
        float* gA = g_Apart + (size_t)blk * M_MOL * P;
        #pragma unroll 4
        for (int idx = tid; idx < M_MOL * P; idx += NTHR) gA[idx] = sAcc[idx];
    }

    // ---- grid barrier (sense-reversal; all 125 blocks co-resident) ----
    __threadfence();
    __syncthreads();
    if (tid == 0) {
        unsigned my = *(volatile unsigned*)&g_phase;
        int old = atomicAdd(&g_cnt, 1);
        if (old == NBLK - 1) {
            g_cnt = 0;
            __threadfence();
            atomicAdd(&g_phase, 1u);
        } else if (blk < M_MOL) {
            while (*(volatile unsigned*)&g_phase == my) __nanosleep(32);
        }
        __threadfence();
    }
    __syncthreads();
    if (blk >= M_MOL) return;

    // ---- post: reduce partials, Fs and Es for m = blk ----
    {
        const int m = blk;
        float* sFsx = sm;          // [276]; sQx (27648+) still intact
        float a = 0.0f;
        if (tid < P) {
            #pragma unroll 5
            for (int b = 0; b < NBLK; b++)
                a += g_Apart[((size_t)b * M_MOL + m) * P + tid];
        }
        if (tid == 300) {          // idle thread does scalar sums in parallel
            float s1 = 0.0f, es = 0.0f;
            #pragma unroll 5
            for (int b = 0; b < NBLK; b++) {
                s1 += g_S1part[b * M_MOL + m];
                es += g_Espart[b * M_MOL + m];
            }
            sm[280] = s1;
            out[m] = es * (1.0f / QC);
        }
        __syncthreads();
        if (tid < P) {
            float qx = sQx[tid * M_MOL + m];
            float xs = qx * (1.0f / QC);
            sFsx[tid] = (qx * sm[280] - a) * xs * xs * xs;
        }
        __syncthreads();
        if (tid < NA * 3) {
            int atom = tid / 3, d = tid % 3;
            float ra = Rs[(m * NA + atom) * 3 + d];
            float f = 0.0f;
            #pragma unroll
            for (int b = 0; b < NA; b++) {
                if (b == atom) continue;
                int hi = (atom > b) ? atom : b;
                int lo = (atom > b) ? b : atom;
                int pi = hi * (hi - 1) / 2 + lo;
                f = fmaf(Rs[(m * NA + b) * 3 + d] - ra, sFsx[pi], f);
            }
            out[M_MOL + (m * NA + atom) * 3 + d] = f;
        }
    }
}

// ---------------- entry ----------------
extern "C" void kernel_launch(void* const* d_in, const int* in_sizes, int n_in,
                              void* d_out, int out_size) {
    const float* Rs  = (const float*)d_in[0];
    const float* xst = (const float*)d_in[1];
    const float* Jx  = (const float*)d_in[2];
    float* out = (float*)d_out;

    cudaFuncSetAttribute(k_all, cudaFuncAttributeMaxDynamicSharedMemorySize, SMEM_BYTES);
    k_all<<<NBLK, NTHR, SMEM_BYTES>>>(Rs, xst, Jx, out);
}